// round 2
// baseline (speedup 1.0000x reference)
#include <cuda_runtime.h>
#include <math.h>

// Problem constants
#define BT   1024   // BS*T
#define NEN  64     // entities
#define ED   128    // entity dim
#define HYPD 256    // hypernet hidden
#define NA   16     // agents
#define NHD  4      // heads
#define HD   64     // head dim
#define EMB  32

// -------- global scratch (static device arrays; no allocation) --------
__device__ float g_w1[BT * NA * EMB];
__device__ float g_b1[BT * EMB];
__device__ float g_wf[BT * EMB];
__device__ float g_vv[BT];

struct Ptrs { const float* p[31]; };

// smem layout (floats):
//  sX1   [64*256]  @ 0       (x1; later logits scratch at 0, x3 at +8192)
//  sK    [64*256]  @ 16384   (k; later attn2)
//  sV    [64*256]  @ 32768
//  sEQ   [8192]    @ 49152   (E[64*128]; later sQ[16*256] @ +0, sAttn[16*256] @ +4096)
//  sEm[64], sAm[16], sRed[32] @ 57344
#define SMEM_FLOATS (57344 + 128)

// ---------------------------------------------------------------------
// GEMM: sOut[R][C] = epi( sA[R][K] * gW[C][K]^T + bias )
// 256 threads. lanes map to columns -> smem A reads are warp-broadcast.
// ---------------------------------------------------------------------
template<int R, int C, int K, bool BIAS, bool RELU, bool AMASK>
__device__ __forceinline__ void gemm(const float* __restrict__ sA,
                                     const float* __restrict__ gW,
                                     const float* __restrict__ gB,
                                     float* __restrict__ sOut,
                                     const float* __restrict__ sAm,
                                     int tid)
{
    constexpr int TC  = 4;
    constexpr int NCG = C / TC;               // col groups (64 for C=256, 8 for C=32)
    constexpr int NRG = 256 / NCG;            // row groups
    constexpr int RPG = (R + NRG - 1) / NRG;  // rows per thread

    const int cg = tid % NCG;
    const int rg = tid / NCG;
    const int c0 = cg * TC;
    const int r0 = rg * RPG;
    if (r0 >= R) return;

    float acc[RPG][TC];
#pragma unroll
    for (int r = 0; r < RPG; r++)
#pragma unroll
        for (int c = 0; c < TC; c++) acc[r][c] = 0.f;

    const float* wbase = gW + c0 * K;
#pragma unroll 2
    for (int k0 = 0; k0 < K; k0 += 8) {
        float4 w0[TC], w1[TC];
#pragma unroll
        for (int c = 0; c < TC; c++) {
            const float4* wp = (const float4*)(wbase + c * K + k0);
            w0[c] = wp[0];
            w1[c] = wp[1];
        }
#pragma unroll
        for (int r = 0; r < RPG; r++) {
            if (RPG * NRG > R && (r0 + r) >= R) break;
            const float4* ap = (const float4*)(sA + (r0 + r) * K + k0);
            float4 a0 = ap[0];
            float4 a1 = ap[1];
#pragma unroll
            for (int c = 0; c < TC; c++) {
                acc[r][c] += a0.x * w0[c].x + a0.y * w0[c].y +
                             a0.z * w0[c].z + a0.w * w0[c].w +
                             a1.x * w1[c].x + a1.y * w1[c].y +
                             a1.z * w1[c].z + a1.w * w1[c].w;
            }
        }
    }

#pragma unroll
    for (int r = 0; r < RPG; r++) {
        int rr = r0 + r;
        if (RPG * NRG > R && rr >= R) break;
        float m = 1.f;
        if (AMASK) m = (sAm[rr] != 0.f) ? 0.f : 1.f;
#pragma unroll
        for (int c = 0; c < TC; c++) {
            float v = acc[r][c];
            if (BIAS) v += gB[c0 + c];
            if (RELU) v = fmaxf(v, 0.f);
            v *= m;
            sOut[rr * C + c0 + c] = v;
        }
    }
}

// ---------------------------------------------------------------------
// Fused hypernet kernel: one CTA per (batch element, hypernet index)
// ---------------------------------------------------------------------
extern __shared__ float smem[];

__global__ void __launch_bounds__(256)
hyper_kernel(Ptrs P)
{
    const int b   = blockIdx.x;
    const int h   = blockIdx.y;
    const int tid = threadIdx.x;

    const float* entities = P.p[1];
    const int*   emask    = (const int*)P.p[2];
    const int    base     = 3 + h * 7;
    const float* fc1_w = P.p[base + 0];
    const float* fc1_b = P.p[base + 1];
    const float* qkv_w = P.p[base + 2];
    const float* out_w = P.p[base + 3];
    const float* out_b = P.p[base + 4];
    const float* fc2_w = P.p[base + 5];
    const float* fc2_b = P.p[base + 6];

    float* sX1   = smem;            // 16384
    float* sK    = smem + 16384;    // 16384
    float* sV    = smem + 32768;    // 16384
    float* sEQ   = smem + 49152;    // 8192
    float* sE    = sEQ;             // E: 64x128
    float* sQ    = sEQ;             // later: 16x256
    float* sAttn = sEQ + 4096;      // 16x256
    float* sL    = sX1;             // logits scratch 64x64 (x1 dead by then)
    float* sX3   = sX1 + 8192;      // 16x32
    float* sAttn2= sK;              // 16x256 (k dead by then)
    float* sEm   = smem + 57344;    // 64
    float* sAm   = sEm + 64;        // 16
    float* sRed  = sAm + 16;        // 32

    __shared__ int sAnyZero;
    if (tid == 0) sAnyZero = 0;
    __syncthreads();

    // masks
    if (tid < NEN) {
        int m = emask[b * NEN + tid];
        sEm[tid] = (float)m;
        if (tid < NA) sAm[tid] = (float)m;
        if (m == 0) atomicOr(&sAnyZero, 1);
    }
    // load entities tile (64x128)
    {
        const float4* src = (const float4*)(entities + (size_t)b * NEN * ED);
        float4* dst = (float4*)sE;
        for (int i = tid; i < NEN * ED / 4; i += 256) dst[i] = src[i];
    }
    __syncthreads();

    // fc1: x1 = relu(E @ fc1_w^T + b)        [64 x 256]
    gemm<64, 256, 128, true, true, false>(sE, fc1_w, fc1_b, sX1, nullptr, tid);
    __syncthreads();

    // qkv (no bias): k, v full (64 rows), q only first 16 rows
    gemm<64, 256, 256, false, false, false>(sX1, qkv_w + 256 * 256, nullptr, sK, nullptr, tid);
    gemm<64, 256, 256, false, false, false>(sX1, qkv_w + 512 * 256, nullptr, sV, nullptr, tid);
    gemm<16, 256, 256, false, false, false>(sX1, qkv_w,             nullptr, sQ, nullptr, tid);
    __syncthreads();

    // attention: 64 threads, one per (head, query)
    {
        const int anyZero = sAnyZero;
        if (tid < NHD * NA) {
            const int hh = tid >> 4;
            const int i  = tid & 15;
            const float scale = 0.125f;  // 1/sqrt(64)
            const float am_i = sAm[i];
            const bool allm = (am_i != 0.f) || (anyZero == 0);
            float* lrow = sL + tid * NEN;
            float mx = -1e30f;
            const float* qrow = sQ + i * HYPD + hh * HD;
            for (int j = 0; j < NEN; j++) {
                const bool keep = (am_i == 0.f) && (sEm[j] == 0.f);
                float s = 0.f;
                const float* krow = sK + j * HYPD + hh * HD;
#pragma unroll
                for (int d4 = 0; d4 < HD / 4; d4++) {
                    float4 qv = ((const float4*)qrow)[d4];
                    float4 kv = ((const float4*)krow)[d4];
                    s += qv.x * kv.x + qv.y * kv.y + qv.z * kv.z + qv.w * kv.w;
                }
                float l = keep ? (s * scale) : -1e30f;
                lrow[j] = l;
                mx = fmaxf(mx, l);
            }
            float sum = 0.f;
            for (int j = 0; j < NEN; j++) {
                float e = expf(lrow[j] - mx);
                sum += e;
                lrow[j] = e;
            }
            const float inv = allm ? 0.f : (1.f / sum);
            float acc[HD];
#pragma unroll
            for (int d = 0; d < HD; d++) acc[d] = 0.f;
            for (int j = 0; j < NEN; j++) {
                const float e = lrow[j];
                const float* vrow = sV + j * HYPD + hh * HD;
#pragma unroll
                for (int d4 = 0; d4 < HD / 4; d4++) {
                    float4 v4 = ((const float4*)vrow)[d4];
                    acc[d4 * 4 + 0] += e * v4.x;
                    acc[d4 * 4 + 1] += e * v4.y;
                    acc[d4 * 4 + 2] += e * v4.z;
                    acc[d4 * 4 + 3] += e * v4.w;
                }
            }
            float* arow = sAttn + i * HYPD + hh * HD;
#pragma unroll
            for (int d = 0; d < HD; d++) arow[d] = acc[d] * inv;
        }
    }
    __syncthreads();

    // out projection: attn2 = attn @ out_w^T + out_b, zero masked agents
    gemm<16, 256, 256, true, false, true>(sAttn, out_w, out_b, sAttn2, sAm, tid);
    __syncthreads();

    // fc2: x3 = attn2 @ fc2_w^T + fc2_b, zero masked agents   [16 x 32]
    gemm<16, 32, 256, true, false, true>(sAttn2, fc2_w, fc2_b, sX3, sAm, tid);
    __syncthreads();

    // mode-specific reductions -> global scratch
    if (h == 0) {
        // matrix, abs
        for (int idx = tid; idx < NA * EMB; idx += 256)
            g_w1[(size_t)b * NA * EMB + idx] = fabsf(sX3[idx]);
    } else if (h == 1) {
        // vector: mean over agents
        if (tid < EMB) {
            float s = 0.f;
            for (int i = 0; i < NA; i++) s += sX3[i * EMB + tid];
            g_b1[b * EMB + tid] = s * (1.f / 16.f);
        }
    } else if (h == 2) {
        // vector then abs
        if (tid < EMB) {
            float s = 0.f;
            for (int i = 0; i < NA; i++) s += sX3[i * EMB + tid];
            g_wf[b * EMB + tid] = fabsf(s * (1.f / 16.f));
        }
    } else {
        // scalar: mean over agents and emb
        if (tid < EMB) {
            float s = 0.f;
            for (int i = 0; i < NA; i++) s += sX3[i * EMB + tid];
            sRed[tid] = s;
        }
        __syncthreads();
        if (tid == 0) {
            float t = 0.f;
            for (int e = 0; e < EMB; e++) t += sRed[e];
            g_vv[b] = t * (1.f / 512.f);
        }
    }
}

// ---------------------------------------------------------------------
// Final mixing: y[b] = sum_e elu(qs[b,:]@|w1| + b1)[e] * wf[e] + v
// ---------------------------------------------------------------------
__global__ void mix_kernel(const float* __restrict__ qs, float* __restrict__ out)
{
    int b = blockIdx.x * blockDim.x + threadIdx.x;
    if (b >= BT) return;
    float qv[NA];
#pragma unroll
    for (int a = 0; a < NA; a++) qv[a] = qs[b * NA + a];
    float acc = g_vv[b];
    for (int e = 0; e < EMB; e++) {
        float s = g_b1[b * EMB + e];
#pragma unroll
        for (int a = 0; a < NA; a++) s += qv[a] * g_w1[(b * NA + a) * EMB + e];
        float hdn = (s > 0.f) ? s : expm1f(s);
        acc += hdn * g_wf[b * EMB + e];
    }
    out[b] = acc;
}

// ---------------------------------------------------------------------
extern "C" void kernel_launch(void* const* d_in, const int* in_sizes, int n_in,
                              void* d_out, int out_size)
{
    Ptrs P;
    for (int i = 0; i < 31; i++) P.p[i] = (const float*)d_in[i];

    const size_t smem_bytes = (size_t)SMEM_FLOATS * sizeof(float); // 229,888 B
    cudaFuncSetAttribute(hyper_kernel,
                         cudaFuncAttributeMaxDynamicSharedMemorySize,
                         (int)smem_bytes);

    hyper_kernel<<<dim3(BT, 4), 256, smem_bytes>>>(P);
    mix_kernel<<<4, 256>>>((const float*)d_in[0], (float*)d_out);
}

// round 4
// speedup vs baseline: 2.0660x; 2.0660x over previous
#include <cuda_runtime.h>
#include <math.h>

// Problem constants
#define BT   1024   // BS*T
#define NEN  64     // entities
#define ED   128    // entity dim
#define HYPD 256    // hypernet hidden
#define NA   16     // agents
#define NHD  4      // heads
#define HD   64     // head dim
#define EMB  32
#define NTHR 512

// -------- global scratch (static device arrays; no allocation) --------
__device__ float g_w1[BT * NA * EMB];
__device__ float g_b1[BT * EMB];
__device__ float g_wf[BT * EMB];
__device__ float g_vv[BT];

struct Ptrs { const float* p[31]; };

// smem layout in floats (cap 58112 floats = 232448 B):
//  sX1   @ 0      (64x256 = 16384)   [later: sL 64x65=4160 @0; wtileO @0; sX3 @8192]
//  sK    @ 16384  (64x256)           [later: sAttn2 @16384]
//  sV    @ 32768  (64x256)           [during K-gemm: wtileK @32768]
//  sQ    @ 49152  (16x256 = 4096)    [E 64x128 = 8192 @49152 during fc1]
//  sAttn @ 53248  (16x256 = 4096)    [during V/Q gemm: wtile @53248 (4160)]
//  sEm   @ 57408 (64), sAm @57472 (16), sInv @57488 (64)
#define SMEM_FLOATS 57568

// ---------------------------------------------------------------------
// Stage weight tile: wt[k][c] (stride C+4) <- gW[c][K] rows, k0..k0+KT-1
// ---------------------------------------------------------------------
template<int C, int KT>
__device__ __forceinline__ void stage(const float* __restrict__ gW, int K, int k0,
                                      float* __restrict__ wt, int tid)
{
    constexpr int K4  = KT / 4;
    constexpr int TOT = C * K4;
#pragma unroll
    for (int idx = tid; idx < TOT; idx += NTHR) {
        int c  = idx / K4;
        int k4 = idx % K4;
        float4 w = *(const float4*)(gW + c * K + k0 + 4 * k4);
        wt[(4 * k4 + 0) * (C + 4) + c] = w.x;
        wt[(4 * k4 + 1) * (C + 4) + c] = w.y;
        wt[(4 * k4 + 2) * (C + 4) + c] = w.z;
        wt[(4 * k4 + 3) * (C + 4) + c] = w.w;
    }
}

// ---------------------------------------------------------------------
// Tiled GEMM: sOut[R][C] = epi( sA[R][K] @ gW[C][K]^T + bias )
// Weight tiles staged in smem (wt, (C+4)*KT floats). 512 threads.
// ---------------------------------------------------------------------
template<int R, int C, int K, bool BIAS, bool RELU, bool AMASK>
__device__ __forceinline__ void gemm(const float* __restrict__ sA,
                                     const float* __restrict__ gW,
                                     const float* __restrict__ gB,
                                     float* __restrict__ sOut,
                                     float* __restrict__ wt,
                                     const float* __restrict__ sAm,
                                     int tid)
{
    constexpr int KT  = 16;
    constexpr int NCG = C / 4;
    constexpr int NRG = NTHR / NCG;
    constexpr int RPG = (R + NRG - 1) / NRG;

    const int c0 = (tid % NCG) * 4;
    const int rg = tid / NCG;
    const int r0 = rg * RPG;
    const bool active = (r0 < R);

    float acc[RPG][4];
#pragma unroll
    for (int r = 0; r < RPG; r++)
#pragma unroll
        for (int c = 0; c < 4; c++) acc[r][c] = 0.f;

    for (int k0 = 0; k0 < K; k0 += KT) {
        __syncthreads();
        stage<C, KT>(gW, K, k0, wt, tid);
        __syncthreads();
        if (active) {
#pragma unroll
            for (int k = 0; k < KT; k++) {
                float4 w = *(const float4*)(wt + k * (C + 4) + c0);
#pragma unroll
                for (int r = 0; r < RPG; r++) {
                    float a = sA[(r0 + r) * K + k0 + k];
                    acc[r][0] += a * w.x;
                    acc[r][1] += a * w.y;
                    acc[r][2] += a * w.z;
                    acc[r][3] += a * w.w;
                }
            }
        }
    }

    if (active) {
        float4 bias = make_float4(0.f, 0.f, 0.f, 0.f);
        if (BIAS) bias = *(const float4*)(gB + c0);
#pragma unroll
        for (int r = 0; r < RPG; r++) {
            int rr = r0 + r;
            float m = 1.f;
            if (AMASK) m = (sAm[rr] != 0.f) ? 0.f : 1.f;
            float4 v;
            v.x = acc[r][0] + bias.x;
            v.y = acc[r][1] + bias.y;
            v.z = acc[r][2] + bias.z;
            v.w = acc[r][3] + bias.w;
            if (RELU) {
                v.x = fmaxf(v.x, 0.f); v.y = fmaxf(v.y, 0.f);
                v.z = fmaxf(v.z, 0.f); v.w = fmaxf(v.w, 0.f);
            }
            v.x *= m; v.y *= m; v.z *= m; v.w *= m;
            *(float4*)(sOut + rr * C + c0) = v;
        }
    }
}

// ---------------------------------------------------------------------
// Fused hypernet kernel: one CTA per (batch element, hypernet index)
// ---------------------------------------------------------------------
extern __shared__ float smem[];

__global__ void __launch_bounds__(NTHR)
hyper_kernel(Ptrs P)
{
    const int b   = blockIdx.x;
    const int h   = blockIdx.y;
    const int tid = threadIdx.x;

    const float* entities = P.p[1];
    const int*   emask    = (const int*)P.p[2];
    const int    base     = 3 + h * 7;
    const float* fc1_w = P.p[base + 0];
    const float* fc1_b = P.p[base + 1];
    const float* qkv_w = P.p[base + 2];
    const float* out_w = P.p[base + 3];
    const float* out_b = P.p[base + 4];
    const float* fc2_w = P.p[base + 5];
    const float* fc2_b = P.p[base + 6];

    float* sX1    = smem;             // 16384
    float* sK     = smem + 16384;     // 16384
    float* sV     = smem + 32768;     // 16384
    float* sQ     = smem + 49152;     // 4096 (E 8192 during fc1)
    float* sE     = smem + 49152;
    float* sAttn  = smem + 53248;     // 4096 (wtile V/Q here: 4160)
    float* sL     = sX1;              // 64x65 logits (X1 dead)
    float* sX3    = sX1 + 8192;       // 16x32
    float* sAttn2 = sK;               // 16x256 (K dead)
    float* sEm    = smem + 57408;     // 64
    float* sAm    = smem + 57472;     // 16
    float* sInv   = smem + 57488;     // 64

    __shared__ int sAnyZero;
    if (tid == 0) sAnyZero = 0;
    __syncthreads();

    // masks
    if (tid < NEN) {
        int m = emask[b * NEN + tid];
        sEm[tid] = (float)m;
        if (tid < NA) sAm[tid] = (float)m;
        if (m == 0) atomicOr(&sAnyZero, 1);
    }
    // load entities tile (64x128)
    {
        const float4* src = (const float4*)(entities + (size_t)b * NEN * ED);
        float4* dst = (float4*)sE;
        for (int i = tid; i < NEN * ED / 4; i += NTHR) dst[i] = src[i];
    }
    __syncthreads();

    // fc1: x1 = relu(E @ fc1_w^T + b)   A@sE, wtile@sK, out@sX1
    gemm<64, 256, 128, true, true, false>(sE, fc1_w, fc1_b, sX1, sK, nullptr, tid);
    __syncthreads();

    // K gemm: A@sX1, wtile@sV, out@sK
    gemm<64, 256, 256, false, false, false>(sX1, qkv_w + 256 * 256, nullptr, sK, sV, nullptr, tid);
    __syncthreads();
    // V gemm: A@sX1, wtile@sAttn, out@sV
    gemm<64, 256, 256, false, false, false>(sX1, qkv_w + 512 * 256, nullptr, sV, sAttn, nullptr, tid);
    __syncthreads();
    // Q gemm (16 rows): A@sX1, wtile@sAttn, out@sQ
    gemm<16, 256, 256, false, false, false>(sX1, qkv_w, nullptr, sQ, sAttn, nullptr, tid);
    __syncthreads();

    const int anyZero = sAnyZero;

    // ---------- attention ----------
    // Phase 1: logits. t -> (jg = t>>6, hq = t&63); each thread: 8 j's.
    {
        const int jg = tid >> 6;
        const int hq = tid & 63;
        const int hh = hq >> 4;
        const int i  = hq & 15;
        const float am_i = sAm[i];
        const float scale = 0.125f;  // 1/sqrt(64)

        float4 q4[16];
        const float4* qrow = (const float4*)(sQ + i * HYPD + hh * HD);
#pragma unroll
        for (int d4 = 0; d4 < 16; d4++) q4[d4] = qrow[d4];

#pragma unroll
        for (int jj = 0; jj < 8; jj++) {
            int j = jg * 8 + jj;
            const float4* krow = (const float4*)(sK + j * HYPD + hh * HD);
            float s = 0.f;
#pragma unroll
            for (int d4 = 0; d4 < 16; d4++) {
                float4 kv = krow[d4];
                s += q4[d4].x * kv.x + q4[d4].y * kv.y +
                     q4[d4].z * kv.z + q4[d4].w * kv.w;
            }
            const bool keep = (am_i == 0.f) && (sEm[j] == 0.f);
            sL[hq * 65 + j] = keep ? (s * scale) : -1e30f;
        }
    }
    __syncthreads();

    // Phase 2: softmax per row (64 threads)
    if (tid < 64) {
        const int hq = tid;
        const int i  = hq & 15;
        const float am_i = sAm[i];
        const bool allm = (am_i != 0.f) || (anyZero == 0);
        float* lrow = sL + hq * 65;
        float mx = -1e30f;
        for (int j = 0; j < NEN; j++) mx = fmaxf(mx, lrow[j]);
        float sum = 0.f;
        for (int j = 0; j < NEN; j++) {
            float e = expf(lrow[j] - mx);
            sum += e;
            lrow[j] = e;
        }
        sInv[hq] = allm ? 0.f : (1.f / sum);
    }
    __syncthreads();

    // Phase 3: AV. t -> (dg = t>>6, hq = t&63); each thread: 8 d's.
    {
        const int dg = tid >> 6;
        const int hq = tid & 63;
        const int hh = hq >> 4;
        const int i  = hq & 15;
        const int d0 = dg * 8;
        const float* lrow = sL + hq * 65;
        float acc[8];
#pragma unroll
        for (int d = 0; d < 8; d++) acc[d] = 0.f;
        for (int j = 0; j < NEN; j++) {
            float p = lrow[j];
            const float4* vrow = (const float4*)(sV + j * HYPD + hh * HD + d0);
            float4 va = vrow[0];
            float4 vb = vrow[1];
            acc[0] += p * va.x; acc[1] += p * va.y;
            acc[2] += p * va.z; acc[3] += p * va.w;
            acc[4] += p * vb.x; acc[5] += p * vb.y;
            acc[6] += p * vb.z; acc[7] += p * vb.w;
        }
        const float inv = sInv[hq];
        float* arow = sAttn + i * HYPD + hh * HD + d0;
#pragma unroll
        for (int d = 0; d < 8; d++) arow[d] = acc[d] * inv;
    }
    __syncthreads();

    // out projection: A@sAttn, wtile@sX1 (logits dead), out@sAttn2(=sK)
    gemm<16, 256, 256, true, false, true>(sAttn, out_w, out_b, sAttn2, sX1, sAm, tid);
    __syncthreads();

    // fc2: A@sAttn2, wtile@sX1, out@sX3 (sX1+8192)
    gemm<16, 32, 256, true, false, true>(sAttn2, fc2_w, fc2_b, sX3, sX1, sAm, tid);
    __syncthreads();

    // mode-specific reductions -> global scratch
    if (h == 0) {
        for (int idx = tid; idx < NA * EMB; idx += NTHR)
            g_w1[(size_t)b * NA * EMB + idx] = fabsf(sX3[idx]);
    } else if (h == 1) {
        if (tid < EMB) {
            float s = 0.f;
            for (int i = 0; i < NA; i++) s += sX3[i * EMB + tid];
            g_b1[b * EMB + tid] = s * (1.f / 16.f);
        }
    } else if (h == 2) {
        if (tid < EMB) {
            float s = 0.f;
            for (int i = 0; i < NA; i++) s += sX3[i * EMB + tid];
            g_wf[b * EMB + tid] = fabsf(s * (1.f / 16.f));
        }
    } else {
        if (tid < EMB) {
            float s = 0.f;
            for (int i = 0; i < NA; i++) s += sX3[i * EMB + tid];
            sInv[tid] = s;   // reuse as scratch
        }
        __syncthreads();
        if (tid == 0) {
            float t = 0.f;
            for (int e = 0; e < EMB; e++) t += sInv[e];
            g_vv[b] = t * (1.f / 512.f);
        }
    }
}

// ---------------------------------------------------------------------
// Final mixing: warp per batch element, lane = emb index (EMB==32)
// ---------------------------------------------------------------------
__global__ void __launch_bounds__(256)
mix_kernel(const float* __restrict__ qs, float* __restrict__ out)
{
    const int warp = threadIdx.x >> 5;
    const int lane = threadIdx.x & 31;
    const int b = blockIdx.x * 8 + warp;
    const int e = lane;

    float s = g_b1[b * EMB + e];
#pragma unroll
    for (int a = 0; a < NA; a++)
        s += qs[b * NA + a] * g_w1[(b * NA + a) * EMB + e];
    float hdn = (s > 0.f) ? s : expm1f(s);
    float t = hdn * g_wf[b * EMB + e];
#pragma unroll
    for (int off = 16; off > 0; off >>= 1)
        t += __shfl_xor_sync(0xFFFFFFFF, t, off);
    if (lane == 0) out[b] = t + g_vv[b];
}

// ---------------------------------------------------------------------
extern "C" void kernel_launch(void* const* d_in, const int* in_sizes, int n_in,
                              void* d_out, int out_size)
{
    Ptrs P;
    for (int i = 0; i < 31; i++) P.p[i] = (const float*)d_in[i];

    const size_t smem_bytes = (size_t)SMEM_FLOATS * sizeof(float); // 230,272 B
    cudaFuncSetAttribute(hyper_kernel,
                         cudaFuncAttributeMaxDynamicSharedMemorySize,
                         (int)smem_bytes);

    hyper_kernel<<<dim3(BT, 4), NTHR, smem_bytes>>>(P);
    mix_kernel<<<BT / 8, 256>>>((const float*)d_in[0], (float*)d_out);
}

// round 5
// speedup vs baseline: 2.3505x; 1.1377x over previous
#include <cuda_runtime.h>
#include <math.h>

// Problem constants
#define BT   1024   // BS*T
#define NEN  64     // entities
#define ED   128    // entity dim
#define HYPD 256    // hypernet hidden
#define NA   16     // agents
#define NHD  4      // heads
#define HD   64     // head dim
#define EMB  32
#define NTHR 512

typedef unsigned long long u64;

// ---- packed fp32x2 helpers (Blackwell FFMA2; bitwise == 2x scalar fp32) ----
__device__ __forceinline__ void ffma2(u64 &d, u64 a, u64 b) {
    asm("fma.rn.f32x2 %0, %1, %2, %0;" : "+l"(d) : "l"(a), "l"(b));
}
__device__ __forceinline__ u64 splat2(float x) {
    u64 r; asm("mov.b64 %0, {%1, %1};" : "=l"(r) : "f"(x)); return r;
}
__device__ __forceinline__ u64 pack2(float x, float y) {
    u64 r; asm("mov.b64 %0, {%1, %2};" : "=l"(r) : "f"(x), "f"(y)); return r;
}
__device__ __forceinline__ float2 unpack2(u64 v) {
    float lo, hi; asm("mov.b64 {%0, %1}, %2;" : "=f"(lo), "=f"(hi) : "l"(v));
    return make_float2(lo, hi);
}

// -------- global scratch (static device arrays; no allocation) --------
__device__ float g_w1[BT * NA * EMB];
__device__ float g_b1[BT * EMB];
__device__ float g_wf[BT * EMB];
__device__ float g_vv[BT];

struct Ptrs { const float* p[31]; };

// smem layout in floats (cap 58112 floats = 232448 B): same schedule as R4
#define SMEM_FLOATS 57568

// ---------------------------------------------------------------------
// Tiled GEMM with register-prefetched weight staging + f32x2 FMA.
// sOut[R][C] = epi( sA[R][K] @ gW[C][K]^T + bias ).  512 threads.
// wt layout: [k][C+4]
// ---------------------------------------------------------------------
template<int R, int C, int K, bool BIAS, bool RELU, bool AMASK>
__device__ __forceinline__ void gemm(const float* __restrict__ sA,
                                     const float* __restrict__ gW,
                                     const float* __restrict__ gB,
                                     float* __restrict__ sOut,
                                     float* __restrict__ wt,
                                     const float* __restrict__ sAm,
                                     int tid)
{
    constexpr int KT  = 16;
    constexpr int NCG = C / 4;
    constexpr int NRG = NTHR / NCG;
    constexpr int RPG = (R + NRG - 1) / NRG;
    constexpr int NT  = K / KT;
    constexpr int K4  = KT / 4;                      // 4
    constexpr int TOT = C * K4;                      // float4 tiles per stage
    constexpr int LPT = (TOT + NTHR - 1) / NTHR;     // loads per thread

    const int c0 = (tid % NCG) * 4;
    const int rg = tid / NCG;
    const int r0 = rg * RPG;
    const bool active = (r0 < R);

    // per-thread staging coords
    int sc[LPT], sk4[LPT];
    bool sp[LPT];
#pragma unroll
    for (int l = 0; l < LPT; l++) {
        int idx = tid + l * NTHR;
        sp[l]  = (idx < TOT);
        sc[l]  = (idx < TOT) ? (idx / K4) : 0;
        sk4[l] = (idx < TOT) ? (idx % K4) : 0;
    }

    u64 acc[RPG][2];
#pragma unroll
    for (int r = 0; r < RPG; r++) { acc[r][0] = 0ULL; acc[r][1] = 0ULL; }

    // prologue: fetch tile 0 into registers
    float4 st[LPT];
#pragma unroll
    for (int l = 0; l < LPT; l++)
        if (sp[l]) st[l] = *(const float4*)(gW + sc[l] * K + 4 * sk4[l]);

    for (int t = 0; t < NT; t++) {
        const int k0 = t * KT;
        __syncthreads();   // wt free (previous tile's compute done)
#pragma unroll
        for (int l = 0; l < LPT; l++) {
            if (sp[l]) {
                int c  = sc[l];
                int kb = 4 * sk4[l];
                wt[(kb + 0) * (C + 4) + c] = st[l].x;
                wt[(kb + 1) * (C + 4) + c] = st[l].y;
                wt[(kb + 2) * (C + 4) + c] = st[l].z;
                wt[(kb + 3) * (C + 4) + c] = st[l].w;
            }
        }
        __syncthreads();   // wt visible
        // prefetch next tile (LDG latency hidden behind compute below)
        if (t + 1 < NT) {
#pragma unroll
            for (int l = 0; l < LPT; l++)
                if (sp[l]) st[l] = *(const float4*)(gW + sc[l] * K + (k0 + KT) + 4 * sk4[l]);
        }
        if (active) {
#pragma unroll
            for (int kk = 0; kk < KT; kk += 4) {
                u64 wp[4][2];
#pragma unroll
                for (int j = 0; j < 4; j++) {
                    float4 w = *(const float4*)(wt + (kk + j) * (C + 4) + c0);
                    wp[j][0] = pack2(w.x, w.y);
                    wp[j][1] = pack2(w.z, w.w);
                }
#pragma unroll
                for (int r = 0; r < RPG; r++) {
                    float4 a4 = *(const float4*)(sA + (r0 + r) * K + k0 + kk);
                    u64 a0 = splat2(a4.x), a1 = splat2(a4.y);
                    u64 a2 = splat2(a4.z), a3 = splat2(a4.w);
                    ffma2(acc[r][0], a0, wp[0][0]); ffma2(acc[r][1], a0, wp[0][1]);
                    ffma2(acc[r][0], a1, wp[1][0]); ffma2(acc[r][1], a1, wp[1][1]);
                    ffma2(acc[r][0], a2, wp[2][0]); ffma2(acc[r][1], a2, wp[2][1]);
                    ffma2(acc[r][0], a3, wp[3][0]); ffma2(acc[r][1], a3, wp[3][1]);
                }
            }
        }
    }

    if (active) {
        float4 bias = make_float4(0.f, 0.f, 0.f, 0.f);
        if (BIAS) bias = *(const float4*)(gB + c0);
#pragma unroll
        for (int r = 0; r < RPG; r++) {
            int rr = r0 + r;
            float m = 1.f;
            if (AMASK) m = (sAm[rr] != 0.f) ? 0.f : 1.f;
            float2 p01 = unpack2(acc[r][0]);
            float2 p23 = unpack2(acc[r][1]);
            float4 v;
            v.x = p01.x + bias.x;
            v.y = p01.y + bias.y;
            v.z = p23.x + bias.z;
            v.w = p23.y + bias.w;
            if (RELU) {
                v.x = fmaxf(v.x, 0.f); v.y = fmaxf(v.y, 0.f);
                v.z = fmaxf(v.z, 0.f); v.w = fmaxf(v.w, 0.f);
            }
            v.x *= m; v.y *= m; v.z *= m; v.w *= m;
            *(float4*)(sOut + rr * C + c0) = v;
        }
    }
}

// ---------------------------------------------------------------------
// Fused hypernet kernel: one CTA per (batch element, hypernet index)
// ---------------------------------------------------------------------
extern __shared__ float smem[];

__global__ void __launch_bounds__(NTHR)
hyper_kernel(Ptrs P)
{
    const int b   = blockIdx.x;
    const int h   = blockIdx.y;
    const int tid = threadIdx.x;

    const float* entities = P.p[1];
    const int*   emask    = (const int*)P.p[2];
    const int    base     = 3 + h * 7;
    const float* fc1_w = P.p[base + 0];
    const float* fc1_b = P.p[base + 1];
    const float* qkv_w = P.p[base + 2];
    const float* out_w = P.p[base + 3];
    const float* out_b = P.p[base + 4];
    const float* fc2_w = P.p[base + 5];
    const float* fc2_b = P.p[base + 6];

    float* sX1    = smem;             // 16384
    float* sK     = smem + 16384;     // 16384
    float* sV     = smem + 32768;     // 16384
    float* sQ     = smem + 49152;     // 4096 (E 8192 during fc1)
    float* sE     = smem + 49152;
    float* sAttn  = smem + 53248;     // 4096 (wtile V/Q here: 4160)
    float* sL     = sX1;              // 64x65 logits (X1 dead)
    float* sX3    = sX1 + 8192;       // 16x32
    float* sAttn2 = sK;               // 16x256 (K dead)
    float* sEm    = smem + 57408;     // 64
    float* sAm    = smem + 57472;     // 16
    float* sInv   = smem + 57488;     // 64

    __shared__ int sAnyZero;
    if (tid == 0) sAnyZero = 0;
    __syncthreads();

    // masks
    if (tid < NEN) {
        int m = emask[b * NEN + tid];
        sEm[tid] = (float)m;
        if (tid < NA) sAm[tid] = (float)m;
        if (m == 0) atomicOr(&sAnyZero, 1);
    }
    // load entities tile (64x128)
    {
        const float4* src = (const float4*)(entities + (size_t)b * NEN * ED);
        float4* dst = (float4*)sE;
        for (int i = tid; i < NEN * ED / 4; i += NTHR) dst[i] = src[i];
    }
    __syncthreads();

    // fc1: x1 = relu(E @ fc1_w^T + b)   A@sE, wtile@sK, out@sX1
    gemm<64, 256, 128, true, true, false>(sE, fc1_w, fc1_b, sX1, sK, nullptr, tid);
    __syncthreads();

    // K gemm: A@sX1, wtile@sV, out@sK
    gemm<64, 256, 256, false, false, false>(sX1, qkv_w + 256 * 256, nullptr, sK, sV, nullptr, tid);
    __syncthreads();
    // V gemm: A@sX1, wtile@sAttn, out@sV
    gemm<64, 256, 256, false, false, false>(sX1, qkv_w + 512 * 256, nullptr, sV, sAttn, nullptr, tid);
    __syncthreads();
    // Q gemm (16 rows): A@sX1, wtile@sAttn, out@sQ
    gemm<16, 256, 256, false, false, false>(sX1, qkv_w, nullptr, sQ, sAttn, nullptr, tid);
    __syncthreads();

    const int anyZero = sAnyZero;

    // ---------- attention ----------
    // Phase 1: logits. t -> (jg = t>>6, hq = t&63); each thread: 8 j's.
    {
        const int jg = tid >> 6;
        const int hq = tid & 63;
        const int hh = hq >> 4;
        const int i  = hq & 15;
        const float am_i = sAm[i];
        const float scale = 0.125f;  // 1/sqrt(64)

        u64 qp[32];
        const float4* qrow = (const float4*)(sQ + i * HYPD + hh * HD);
#pragma unroll
        for (int d4 = 0; d4 < 16; d4++) {
            float4 q = qrow[d4];
            qp[2 * d4 + 0] = pack2(q.x, q.y);
            qp[2 * d4 + 1] = pack2(q.z, q.w);
        }

#pragma unroll
        for (int jj = 0; jj < 8; jj++) {
            int j = jg * 8 + jj;
            const float4* krow = (const float4*)(sK + j * HYPD + hh * HD);
            u64 a0 = 0ULL, a1 = 0ULL;
#pragma unroll
            for (int d4 = 0; d4 < 16; d4++) {
                float4 kv = krow[d4];
                ffma2(a0, qp[2 * d4 + 0], pack2(kv.x, kv.y));
                ffma2(a1, qp[2 * d4 + 1], pack2(kv.z, kv.w));
            }
            float2 f0 = unpack2(a0);
            float2 f1 = unpack2(a1);
            float s = (f0.x + f0.y) + (f1.x + f1.y);
            const bool keep = (am_i == 0.f) && (sEm[j] == 0.f);
            sL[hq * 65 + j] = keep ? (s * scale) : -1e30f;
        }
    }
    __syncthreads();

    // Phase 2: softmax per row (64 threads)
    if (tid < 64) {
        const int hq = tid;
        const int i  = hq & 15;
        const float am_i = sAm[i];
        const bool allm = (am_i != 0.f) || (anyZero == 0);
        float* lrow = sL + hq * 65;
        float mx = -1e30f;
        for (int j = 0; j < NEN; j++) mx = fmaxf(mx, lrow[j]);
        float sum = 0.f;
        for (int j = 0; j < NEN; j++) {
            float e = expf(lrow[j] - mx);
            sum += e;
            lrow[j] = e;
        }
        sInv[hq] = allm ? 0.f : (1.f / sum);
    }
    __syncthreads();

    // Phase 3: AV. t -> (dg = t>>6, hq = t&63); each thread: 8 d's.
    {
        const int dg = tid >> 6;
        const int hq = tid & 63;
        const int hh = hq >> 4;
        const int i  = hq & 15;
        const int d0 = dg * 8;
        const float* lrow = sL + hq * 65;
        u64 acc[4] = {0ULL, 0ULL, 0ULL, 0ULL};
        for (int j = 0; j < NEN; j++) {
            u64 ps = splat2(lrow[j]);
            const float4* vrow = (const float4*)(sV + j * HYPD + hh * HD + d0);
            float4 va = vrow[0];
            float4 vb = vrow[1];
            ffma2(acc[0], ps, pack2(va.x, va.y));
            ffma2(acc[1], ps, pack2(va.z, va.w));
            ffma2(acc[2], ps, pack2(vb.x, vb.y));
            ffma2(acc[3], ps, pack2(vb.z, vb.w));
        }
        const float inv = sInv[hq];
        float* arow = sAttn + i * HYPD + hh * HD + d0;
#pragma unroll
        for (int q = 0; q < 4; q++) {
            float2 f = unpack2(acc[q]);
            arow[2 * q + 0] = f.x * inv;
            arow[2 * q + 1] = f.y * inv;
        }
    }
    __syncthreads();

    // out projection: A@sAttn, wtile@sX1 (logits dead), out@sAttn2(=sK)
    gemm<16, 256, 256, true, false, true>(sAttn, out_w, out_b, sAttn2, sX1, sAm, tid);
    __syncthreads();

    // fc2: A@sAttn2, wtile@sX1, out@sX3 (sX1+8192)
    gemm<16, 32, 256, true, false, true>(sAttn2, fc2_w, fc2_b, sX3, sX1, sAm, tid);
    __syncthreads();

    // mode-specific reductions -> global scratch
    if (h == 0) {
        for (int idx = tid; idx < NA * EMB; idx += NTHR)
            g_w1[(size_t)b * NA * EMB + idx] = fabsf(sX3[idx]);
    } else if (h == 1) {
        if (tid < EMB) {
            float s = 0.f;
            for (int i = 0; i < NA; i++) s += sX3[i * EMB + tid];
            g_b1[b * EMB + tid] = s * (1.f / 16.f);
        }
    } else if (h == 2) {
        if (tid < EMB) {
            float s = 0.f;
            for (int i = 0; i < NA; i++) s += sX3[i * EMB + tid];
            g_wf[b * EMB + tid] = fabsf(s * (1.f / 16.f));
        }
    } else {
        if (tid < EMB) {
            float s = 0.f;
            for (int i = 0; i < NA; i++) s += sX3[i * EMB + tid];
            sInv[tid] = s;   // reuse as scratch
        }
        __syncthreads();
        if (tid == 0) {
            float t = 0.f;
            for (int e = 0; e < EMB; e++) t += sInv[e];
            g_vv[b] = t * (1.f / 512.f);
        }
    }
}

// ---------------------------------------------------------------------
// Final mixing: warp per batch element, lane = emb index (EMB==32)
// ---------------------------------------------------------------------
__global__ void __launch_bounds__(256)
mix_kernel(const float* __restrict__ qs, float* __restrict__ out)
{
    const int warp = threadIdx.x >> 5;
    const int lane = threadIdx.x & 31;
    const int b = blockIdx.x * 8 + warp;
    const int e = lane;

    float s = g_b1[b * EMB + e];
#pragma unroll
    for (int a = 0; a < NA; a++)
        s += qs[b * NA + a] * g_w1[(b * NA + a) * EMB + e];
    float hdn = (s > 0.f) ? s : expm1f(s);
    float t = hdn * g_wf[b * EMB + e];
#pragma unroll
    for (int off = 16; off > 0; off >>= 1)
        t += __shfl_xor_sync(0xFFFFFFFF, t, off);
    if (lane == 0) out[b] = t + g_vv[b];
}

// ---------------------------------------------------------------------
extern "C" void kernel_launch(void* const* d_in, const int* in_sizes, int n_in,
                              void* d_out, int out_size)
{
    Ptrs P;
    for (int i = 0; i < 31; i++) P.p[i] = (const float*)d_in[i];

    const size_t smem_bytes = (size_t)SMEM_FLOATS * sizeof(float); // 230,272 B
    cudaFuncSetAttribute(hyper_kernel,
                         cudaFuncAttributeMaxDynamicSharedMemorySize,
                         (int)smem_bytes);

    hyper_kernel<<<dim3(BT, 4), NTHR, smem_bytes>>>(P);
    mix_kernel<<<BT / 8, 256>>>((const float*)d_in[0], (float*)d_out);
}